// round 4
// baseline (speedup 1.0000x reference)
#include <cuda_runtime.h>
#include <math.h>

// Problem constants
#define BATCH 32
#define CIN   64
#define HIN   128
#define WIN   128
#define COUT  128
#define HO    126
#define WO    126
#define NGRP  16          // 16 groups, 8 channels each
#define HP    63          // pooled H
#define WP    63          // pooled W
#define GN_N  (8 * HO * WO)   // elements per (b, group) = 127008

// Conv tiling
#define BC 64             // couts per block
#define BT 16             // spatial tile (BT x BT outputs)
#define CK 8              // cin per chunk
#define NCK (CIN / CK)    // 8 chunks
#define KSTEPS (CK * 9)   // 72 k-steps per chunk
#define XS_W 20           // padded row stride in xs
#define XS_ROW (18 * XS_W)  // 360 floats per cin plane

// Scratch (device globals; no runtime allocation allowed)
__device__ float g_y[(size_t)BATCH * COUT * HO * WO];   // conv output, ~260 MB
__device__ float g_wt[CIN * 9 * COUT];                  // transposed weights [k][cout]
__device__ float g_psum[BATCH * NGRP * 64];             // per-tile partial sums
__device__ float g_psq [BATCH * NGRP * 64];             // per-tile partial sumsq
__device__ float g_mean[BATCH * NGRP];
__device__ float g_rstd[BATCH * NGRP];

// ---------------------------------------------------------------------------
// Prep: transpose conv_w (O,I,3,3) -> g_wt[(cin*9 + kh*3 + kw)][cout]
// ---------------------------------------------------------------------------
__global__ void prep_kernel(const float* __restrict__ conv_w) {
    int idx = blockIdx.x * blockDim.x + threadIdx.x;
    if (idx < CIN * 9 * COUT) {
        int k  = idx / COUT;        // cin*9 + r
        int co = idx - k * COUT;
        int ci = k / 9;
        int r  = k - ci * 9;        // kh*3 + kw
        g_wt[idx] = conv_w[(co * CIN + ci) * 9 + r];
    }
}

// ---------------------------------------------------------------------------
// Conv 3x3 valid, fp32, SGEMM-style register blocking.
// Block: 64 couts x 16x16 spatial. Thread: 8 couts x 8 spatial positions.
// Warp (32 lanes) = one cout-group (weights broadcast via smem).
// Spatial per thread: p_s = 32*s + ts  (s=0..7), i.e. row = 2s + (ts>>4),
// col = ts & 15 -> lane-consecutive smem addresses, coalesced stores.
// Also emits deterministic per-(b,group) partial sum/sumsq (no atomics).
// ---------------------------------------------------------------------------
__global__ __launch_bounds__(256, 2)
void conv_kernel(const float* __restrict__ x, const float* __restrict__ conv_b) {
    __shared__ __align__(16) float xs[CK * XS_ROW];     // 2880 floats
    __shared__ __align__(16) float ws[KSTEPS * BC];     // 4608 floats

    const int t  = threadIdx.x;
    const int bw = blockIdx.x;          // 0..7 (w tiles)
    const int bh = blockIdx.y;          // 0..7 (h tiles)
    const int bz = blockIdx.z;          // b*2 + coutTile
    const int b  = bz >> 1;
    const int c0 = (bz & 1) * BC;
    const int h0 = bh * BT;
    const int w0 = bw * BT;

    const int tc = t >> 5;              // 0..7  cout sub-group (== warp id)
    const int ts = t & 31;              // lane
    const int lr = ts >> 4;             // 0..1  row offset within pair
    const int lc = ts & 15;             // 0..15 col

    float acc[8][8];
#pragma unroll
    for (int i = 0; i < 8; i++)
#pragma unroll
        for (int j = 0; j < 8; j++) acc[i][j] = 0.f;

    const float* xb = x + (size_t)b * CIN * HIN * WIN;

    for (int ck = 0; ck < NCK; ck++) {
        __syncthreads();
        // --- load x tile: CK x 18 x 18 (guarded at image edge) ---
        for (int idx = t; idx < CK * 18 * 18; idx += 256) {
            int ci  = idx / 324;
            int rem = idx - ci * 324;
            int i   = rem / 18;
            int j   = rem - i * 18;
            int h = h0 + i, w = w0 + j;
            float v = 0.f;
            if (h < HIN && w < WIN)
                v = xb[((size_t)(ck * CK + ci) * HIN + h) * WIN + w];
            xs[ci * XS_ROW + i * XS_W + j] = v;
        }
        // --- load weight tile: 72 x 64, coalesced from transposed layout ---
        for (int idx = t; idx < KSTEPS * BC; idx += 256) {
            int kk = idx >> 6;
            int cl = idx & 63;
            ws[idx] = g_wt[(ck * KSTEPS + kk) * COUT + c0 + cl];
        }
        __syncthreads();

        const float* xbase = xs + lr * XS_W + lc;
#pragma unroll 1
        for (int ci = 0; ci < CK; ci++) {
#pragma unroll
            for (int kh = 0; kh < 3; kh++) {
#pragma unroll
                for (int kw = 0; kw < 3; kw++) {
                    const int kk = ci * 9 + kh * 3 + kw;
                    float4 wa = *(const float4*)(ws + kk * BC + tc * 8);
                    float4 wb = *(const float4*)(ws + kk * BC + tc * 8 + 4);
                    float wv[8] = {wa.x, wa.y, wa.z, wa.w, wb.x, wb.y, wb.z, wb.w};
                    const float* xp = xbase + ci * XS_ROW + kh * XS_W + kw;
                    float xv[8];
#pragma unroll
                    for (int s = 0; s < 8; s++) xv[s] = xp[2 * s * XS_W];
#pragma unroll
                    for (int co = 0; co < 8; co++)
#pragma unroll
                        for (int s = 0; s < 8; s++)
                            acc[co][s] = fmaf(wv[co], xv[s], acc[co][s]);
                }
            }
        }
    }

    // --- epilogue: bias add, store y, accumulate group sums ---
    const int g = (c0 >> 3) + tc;       // all 8 couts of this thread share group g
    const int ow = w0 + lc;
    float lsum = 0.f, lsq = 0.f;
#pragma unroll
    for (int co = 0; co < 8; co++) {
        const int cout = c0 + tc * 8 + co;
        const float bias = conv_b[cout];
        float* yrow = g_y + ((size_t)b * COUT + cout) * (size_t)(HO * WO);
#pragma unroll
        for (int s = 0; s < 8; s++) {
            const int oh = h0 + 2 * s + lr;
            if (oh < HO && ow < WO) {
                float v = acc[co][s] + bias;
                yrow[oh * WO + ow] = v;
                lsum += v;
                lsq  += v * v;
            }
        }
    }
    // warp reduction (warp == cout-group == one GN group)
#pragma unroll
    for (int off = 16; off > 0; off >>= 1) {
        lsum += __shfl_xor_sync(0xffffffffu, lsum, off);
        lsq  += __shfl_xor_sync(0xffffffffu, lsq,  off);
    }
    if (ts == 0) {
        const int tile = bh * 8 + bw;   // 0..63, unique per (b,g)
        g_psum[(b * NGRP + g) * 64 + tile] = lsum;
        g_psq [(b * NGRP + g) * 64 + tile] = lsq;
    }
}

// ---------------------------------------------------------------------------
// Stats: fold 64 tile-partials per (b,g) -> mean, rstd  (deterministic order)
// ---------------------------------------------------------------------------
__global__ void stats_kernel() {
    int i = blockIdx.x * blockDim.x + threadIdx.x;
    if (i < BATCH * NGRP) {
        float s = 0.f, q = 0.f;
        const float* ps = g_psum + i * 64;
        const float* pq = g_psq  + i * 64;
#pragma unroll 8
        for (int tile = 0; tile < 64; tile++) { s += ps[tile]; q += pq[tile]; }
        const float invN = 1.f / (float)GN_N;
        float mean = s * invN;
        float var  = q * invN - mean * mean;
        g_mean[i] = mean;
        g_rstd[i] = rsqrtf(var + 1e-5f);
    }
}

// ---------------------------------------------------------------------------
// Fused normalize * gn_w + gn_b, * scale, 2x2 maxpool, clamp[0,1]
// ---------------------------------------------------------------------------
__global__ void pool_kernel(const float* __restrict__ gn_w,
                            const float* __restrict__ gn_b,
                            const float* __restrict__ scale,
                            float* __restrict__ out) {
    int idx = blockIdx.x * blockDim.x + threadIdx.x;
    if (idx >= BATCH * COUT * HP * WP) return;
    int ow  = idx % WP;
    int tmp = idx / WP;
    int oh  = tmp % HP;
    tmp    /= HP;
    int c   = tmp % COUT;
    int b   = tmp / COUT;

    const int bg = b * NGRP + (c >> 3);
    const float mean = g_mean[bg];
    const float rstd = g_rstd[bg];
    const float a  = rstd * gn_w[c] * scale[c];
    const float bb = (gn_b[c] - mean * rstd * gn_w[c]) * scale[c];

    const float* yp = g_y + (((size_t)b * COUT + c) * HO + oh * 2) * (size_t)WO + ow * 2;
    float v0 = fmaf(a, yp[0],      bb);
    float v1 = fmaf(a, yp[1],      bb);
    float v2 = fmaf(a, yp[WO],     bb);
    float v3 = fmaf(a, yp[WO + 1], bb);
    float m = fmaxf(fmaxf(v0, v1), fmaxf(v2, v3));
    out[idx] = fminf(fmaxf(m, 0.0f), 1.0f);
}

// ---------------------------------------------------------------------------
extern "C" void kernel_launch(void* const* d_in, const int* in_sizes, int n_in,
                              void* d_out, int out_size) {
    const float* x      = (const float*)d_in[0];
    const float* conv_w = (const float*)d_in[1];
    const float* conv_b = (const float*)d_in[2];
    const float* gn_w   = (const float*)d_in[3];
    const float* gn_b   = (const float*)d_in[4];
    const float* scale  = (const float*)d_in[5];
    float* out = (float*)d_out;

    prep_kernel<<<(CIN * 9 * COUT + 255) / 256, 256>>>(conv_w);
    conv_kernel<<<dim3(8, 8, BATCH * 2), 256>>>(x, conv_b);
    stats_kernel<<<2, 256>>>();
    const int npool = BATCH * COUT * HP * WP;     // 16,257,024
    pool_kernel<<<(npool + 255) / 256, 256>>>(gn_w, gn_b, scale, out);
}

// round 5
// speedup vs baseline: 1.0002x; 1.0002x over previous
#include <cuda_runtime.h>
#include <math.h>

// Problem constants
#define BATCH 32
#define CIN   64
#define HIN   128
#define WIN   128
#define COUT  128
#define HO    126
#define WO    126
#define NGRP  16          // 16 groups, 8 channels each
#define HP    63          // pooled H
#define WP    63          // pooled W
#define GN_N  (8 * HO * WO)   // elements per (b, group) = 127008

// Conv tiling
#define BC 64             // couts per block
#define BT 16             // spatial tile (BT x BT outputs)
#define CK 8              // cin per chunk
#define NCK (CIN / CK)    // 8 chunks
#define KSTEPS (CK * 9)   // 72 k-steps per chunk
#define XS_W 20           // padded row stride in xs
#define XS_ROW (18 * XS_W)  // 360 floats per cin plane

// Scratch (device globals; no runtime allocation allowed)
__device__ float g_y[(size_t)BATCH * COUT * HO * WO];   // conv output, ~260 MB
__device__ float g_wt[CIN * 9 * COUT];                  // transposed weights [k][cout]
__device__ float g_psum[BATCH * NGRP * 64];             // per-tile partial sums
__device__ float g_psq [BATCH * NGRP * 64];             // per-tile partial sumsq
__device__ float g_mean[BATCH * NGRP];
__device__ float g_rstd[BATCH * NGRP];

// ---------------------------------------------------------------------------
// Prep: transpose conv_w (O,I,3,3) -> g_wt[(cin*9 + kh*3 + kw)][cout]
// ---------------------------------------------------------------------------
__global__ void prep_kernel(const float* __restrict__ conv_w) {
    int idx = blockIdx.x * blockDim.x + threadIdx.x;
    if (idx < CIN * 9 * COUT) {
        int k  = idx / COUT;        // cin*9 + r
        int co = idx - k * COUT;
        int ci = k / 9;
        int r  = k - ci * 9;        // kh*3 + kw
        g_wt[idx] = conv_w[(co * CIN + ci) * 9 + r];
    }
}

// ---------------------------------------------------------------------------
// Conv 3x3 valid, fp32, SGEMM-style register blocking.
// Block: 64 couts x 16x16 spatial. Thread: 8 couts x 8 spatial positions.
// Warp (32 lanes) = one cout-group (weights broadcast via smem).
// Spatial per thread: p_s = 32*s + ts  (s=0..7), i.e. row = 2s + (ts>>4),
// col = ts & 15 -> lane-consecutive smem addresses, coalesced stores.
// Also emits deterministic per-(b,group) partial sum/sumsq (no atomics).
// ---------------------------------------------------------------------------
__global__ __launch_bounds__(256, 2)
void conv_kernel(const float* __restrict__ x, const float* __restrict__ conv_b) {
    __shared__ __align__(16) float xs[CK * XS_ROW];     // 2880 floats
    __shared__ __align__(16) float ws[KSTEPS * BC];     // 4608 floats

    const int t  = threadIdx.x;
    const int bw = blockIdx.x;          // 0..7 (w tiles)
    const int bh = blockIdx.y;          // 0..7 (h tiles)
    const int bz = blockIdx.z;          // b*2 + coutTile
    const int b  = bz >> 1;
    const int c0 = (bz & 1) * BC;
    const int h0 = bh * BT;
    const int w0 = bw * BT;

    const int tc = t >> 5;              // 0..7  cout sub-group (== warp id)
    const int ts = t & 31;              // lane
    const int lr = ts >> 4;             // 0..1  row offset within pair
    const int lc = ts & 15;             // 0..15 col

    float acc[8][8];
#pragma unroll
    for (int i = 0; i < 8; i++)
#pragma unroll
        for (int j = 0; j < 8; j++) acc[i][j] = 0.f;

    const float* xb = x + (size_t)b * CIN * HIN * WIN;

    for (int ck = 0; ck < NCK; ck++) {
        __syncthreads();
        // --- load x tile: CK x 18 x 18 (guarded at image edge) ---
        for (int idx = t; idx < CK * 18 * 18; idx += 256) {
            int ci  = idx / 324;
            int rem = idx - ci * 324;
            int i   = rem / 18;
            int j   = rem - i * 18;
            int h = h0 + i, w = w0 + j;
            float v = 0.f;
            if (h < HIN && w < WIN)
                v = xb[((size_t)(ck * CK + ci) * HIN + h) * WIN + w];
            xs[ci * XS_ROW + i * XS_W + j] = v;
        }
        // --- load weight tile: 72 x 64, coalesced from transposed layout ---
        for (int idx = t; idx < KSTEPS * BC; idx += 256) {
            int kk = idx >> 6;
            int cl = idx & 63;
            ws[idx] = g_wt[(ck * KSTEPS + kk) * COUT + c0 + cl];
        }
        __syncthreads();

        const float* xbase = xs + lr * XS_W + lc;
#pragma unroll 1
        for (int ci = 0; ci < CK; ci++) {
#pragma unroll
            for (int kh = 0; kh < 3; kh++) {
#pragma unroll
                for (int kw = 0; kw < 3; kw++) {
                    const int kk = ci * 9 + kh * 3 + kw;
                    float4 wa = *(const float4*)(ws + kk * BC + tc * 8);
                    float4 wb = *(const float4*)(ws + kk * BC + tc * 8 + 4);
                    float wv[8] = {wa.x, wa.y, wa.z, wa.w, wb.x, wb.y, wb.z, wb.w};
                    const float* xp = xbase + ci * XS_ROW + kh * XS_W + kw;
                    float xv[8];
#pragma unroll
                    for (int s = 0; s < 8; s++) xv[s] = xp[2 * s * XS_W];
#pragma unroll
                    for (int co = 0; co < 8; co++)
#pragma unroll
                        for (int s = 0; s < 8; s++)
                            acc[co][s] = fmaf(wv[co], xv[s], acc[co][s]);
                }
            }
        }
    }

    // --- epilogue: bias add, store y, accumulate group sums ---
    const int g = (c0 >> 3) + tc;       // all 8 couts of this thread share group g
    const int ow = w0 + lc;
    float lsum = 0.f, lsq = 0.f;
#pragma unroll
    for (int co = 0; co < 8; co++) {
        const int cout = c0 + tc * 8 + co;
        const float bias = conv_b[cout];
        float* yrow = g_y + ((size_t)b * COUT + cout) * (size_t)(HO * WO);
#pragma unroll
        for (int s = 0; s < 8; s++) {
            const int oh = h0 + 2 * s + lr;
            if (oh < HO && ow < WO) {
                float v = acc[co][s] + bias;
                yrow[oh * WO + ow] = v;
                lsum += v;
                lsq  += v * v;
            }
        }
    }
    // warp reduction (warp == cout-group == one GN group)
#pragma unroll
    for (int off = 16; off > 0; off >>= 1) {
        lsum += __shfl_xor_sync(0xffffffffu, lsum, off);
        lsq  += __shfl_xor_sync(0xffffffffu, lsq,  off);
    }
    if (ts == 0) {
        const int tile = bh * 8 + bw;   // 0..63, unique per (b,g)
        g_psum[(b * NGRP + g) * 64 + tile] = lsum;
        g_psq [(b * NGRP + g) * 64 + tile] = lsq;
    }
}

// ---------------------------------------------------------------------------
// Stats: fold 64 tile-partials per (b,g) -> mean, rstd  (deterministic order)
// ---------------------------------------------------------------------------
__global__ void stats_kernel() {
    int i = blockIdx.x * blockDim.x + threadIdx.x;
    if (i < BATCH * NGRP) {
        float s = 0.f, q = 0.f;
        const float* ps = g_psum + i * 64;
        const float* pq = g_psq  + i * 64;
#pragma unroll 8
        for (int tile = 0; tile < 64; tile++) { s += ps[tile]; q += pq[tile]; }
        const float invN = 1.f / (float)GN_N;
        float mean = s * invN;
        float var  = q * invN - mean * mean;
        g_mean[i] = mean;
        g_rstd[i] = rsqrtf(var + 1e-5f);
    }
}

// ---------------------------------------------------------------------------
// Fused normalize * gn_w + gn_b, * scale, 2x2 maxpool, clamp[0,1]
// ---------------------------------------------------------------------------
__global__ void pool_kernel(const float* __restrict__ gn_w,
                            const float* __restrict__ gn_b,
                            const float* __restrict__ scale,
                            float* __restrict__ out) {
    int idx = blockIdx.x * blockDim.x + threadIdx.x;
    if (idx >= BATCH * COUT * HP * WP) return;
    int ow  = idx % WP;
    int tmp = idx / WP;
    int oh  = tmp % HP;
    tmp    /= HP;
    int c   = tmp % COUT;
    int b   = tmp / COUT;

    const int bg = b * NGRP + (c >> 3);
    const float mean = g_mean[bg];
    const float rstd = g_rstd[bg];
    const float a  = rstd * gn_w[c] * scale[c];
    const float bb = (gn_b[c] - mean * rstd * gn_w[c]) * scale[c];

    const float* yp = g_y + (((size_t)b * COUT + c) * HO + oh * 2) * (size_t)WO + ow * 2;
    float v0 = fmaf(a, yp[0],      bb);
    float v1 = fmaf(a, yp[1],      bb);
    float v2 = fmaf(a, yp[WO],     bb);
    float v3 = fmaf(a, yp[WO + 1], bb);
    float m = fmaxf(fmaxf(v0, v1), fmaxf(v2, v3));
    out[idx] = fminf(fmaxf(m, 0.0f), 1.0f);
}

// ---------------------------------------------------------------------------
extern "C" void kernel_launch(void* const* d_in, const int* in_sizes, int n_in,
                              void* d_out, int out_size) {
    const float* x      = (const float*)d_in[0];
    const float* conv_w = (const float*)d_in[1];
    const float* conv_b = (const float*)d_in[2];
    const float* gn_w   = (const float*)d_in[3];
    const float* gn_b   = (const float*)d_in[4];
    const float* scale  = (const float*)d_in[5];
    float* out = (float*)d_out;

    prep_kernel<<<(CIN * 9 * COUT + 255) / 256, 256>>>(conv_w);
    conv_kernel<<<dim3(8, 8, BATCH * 2), 256>>>(x, conv_b);
    stats_kernel<<<2, 256>>>();
    const int npool = BATCH * COUT * HP * WP;     // 16,257,024
    pool_kernel<<<(npool + 255) / 256, 256>>>(gn_w, gn_b, scale, out);
}

// round 7
// speedup vs baseline: 1.4211x; 1.4209x over previous
#include <cuda_runtime.h>
#include <cuda_bf16.h>
#include <cstdint>
#include <math.h>

// ---------------- problem constants ----------------
#define BATCH 32
#define CIN   64
#define HWIN  16384
#define COUT  128
#define HO    126
#define WO    126
#define NGRP  16
#define HP    63
#define WP    63
#define NTILE 63
#define GN_N  (8 * HO * WO)

// W tile: per tap, [co][33 u32] (32 data + 1 pad), hi then lo: 8448 u32 = 33792 B
#define WTAP_U32 8448
#define WTAP_B   33792

// smem layout (bytes):
//  [0,512)        bias (128 f)
//  [512,768)      sRed  (64 f)
//  [768,1024)     sRedQ (64 f)
//  [1024,+67584)  W ping-pong: 2 bufs x 33792 B
//  [68608,+67848) slab hi: 514*33 u32
//  [136456,+67848) slab lo
#define SM_W     1024
#define SM_SLABH 68608
#define SM_SLABL 136456
#define SMEM_TOTAL 204304

// ---------------- helpers ----------------
__device__ __forceinline__ uint32_t smem_u32(const void* p) {
    uint32_t a;
    asm("{ .reg .u64 t; cvta.to.shared.u64 t, %1; cvt.u32.u64 %0, t; }" : "=r"(a) : "l"(p));
    return a;
}
#define CP_ASYNC16(dst_u32, src_ptr) \
    asm volatile("cp.async.cg.shared.global [%0], [%1], 16;" :: "r"(dst_u32), "l"(src_ptr) : "memory")
#define CP_COMMIT() asm volatile("cp.async.commit_group;" ::: "memory")
#define CP_WAIT0()  asm volatile("cp.async.wait_group 0;" ::: "memory")

__device__ __forceinline__ void mma16816(float* c, const uint32_t* a, const uint32_t* b) {
    asm volatile(
        "mma.sync.aligned.m16n8k16.row.col.f32.bf16.bf16.f32 "
        "{%0,%1,%2,%3}, {%4,%5,%6,%7}, {%8,%9}, {%0,%1,%2,%3};"
        : "+f"(c[0]), "+f"(c[1]), "+f"(c[2]), "+f"(c[3])
        : "r"(a[0]), "r"(a[1]), "r"(a[2]), "r"(a[3]), "r"(b[0]), "r"(b[1]));
}

// ---------------- device scratch ----------------
__device__ float g_y[(size_t)BATCH * COUT * HO * WO];            // [b][co][h][w]
__device__ __align__(16) uint32_t g_w[9 * WTAP_U32];             // per-tap swizzled bf16 hi/lo
__device__ float g_psum[BATCH * NGRP * NTILE];
__device__ float g_psq [BATCH * NGRP * NTILE];
__device__ float g_mean[BATCH * NGRP];
__device__ float g_rstd[BATCH * NGRP];

// ---------------------------------------------------------------------------
// Prep: conv_w (O,I,3,3) fp32 -> per-tap [co][swizzled ci-u32] bf16 hi/lo.
// swizzle: u32 index (ci>>1) ^ ((co&7)<<2); pad word zeroed.
// ---------------------------------------------------------------------------
__global__ void prep_kernel(const float* __restrict__ conv_w) {
    int idx = blockIdx.x * 256 + threadIdx.x;
    if (idx >= 9 * COUT * CIN) return;
    int r   = idx / (COUT * CIN);
    int rem = idx - r * (COUT * CIN);
    int co  = rem >> 6;
    int ci  = rem & 63;
    float w = conv_w[(co * CIN + ci) * 9 + r];
    __nv_bfloat16 h = __float2bfloat16(w);
    __nv_bfloat16 l = __float2bfloat16(w - __bfloat162float(h));
    uint32_t swz = (uint32_t)(ci >> 1) ^ (uint32_t)((co & 7) << 2);
    unsigned short* gw = (unsigned short*)g_w;
    gw[(r * WTAP_U32 +        co * 33 + swz) * 2 + (ci & 1)] = *(unsigned short*)&h;
    gw[(r * WTAP_U32 + 4224 + co * 33 + swz) * 2 + (ci & 1)] = *(unsigned short*)&l;
    if (ci == 0) {           // zero pad words (copied by cp.async, never read)
        g_w[r * WTAP_U32 +        co * 33 + 32] = 0;
        g_w[r * WTAP_U32 + 4224 + co * 33 + 32] = 0;
    }
}

// ---------------------------------------------------------------------------
// Conv via mma.sync m16n8k16 bf16, split hi/lo (hh + hl + lh), fp32 acc.
// CTA = (row-pair i, batch b): M=256 pos x N=128 co x K=576.
// Warps: 4(M) x 2(N); warp tile 64x64.
// ---------------------------------------------------------------------------
__global__ __launch_bounds__(256, 1)
void conv_kernel(const float* __restrict__ x, const float* __restrict__ conv_b) {
    extern __shared__ char smem[];
    float*    sBias  = (float*)smem;
    float*    sRed   = (float*)(smem + 512);
    float*    sRedQ  = (float*)(smem + 768);
    uint32_t* sW     = (uint32_t*)(smem + SM_W);
    uint32_t* sSlabH = (uint32_t*)(smem + SM_SLABH);
    uint32_t* sSlabL = (uint32_t*)(smem + SM_SLABL);

    const int t    = threadIdx.x;
    const int wid  = t >> 5;
    const int lane = t & 31;
    const int g    = lane >> 2;
    const int tl   = lane & 3;
    const int wm   = wid & 3;            // M warp index
    const int wn   = wid >> 2;           // N warp index
    const int warp_m = wm * 64;
    const int warp_n = wn * 64;
    const int i  = blockIdx.x;           // row pair: output rows 2i, 2i+1
    const int b  = blockIdx.y;
    const int p0 = i * 256;

    const uint32_t sW_addr = smem_u32(sW);

    // prefetch W tap 0 -> buf 0
    {
        const char* src = (const char*)g_w;
        for (int j = t; j < 2112; j += 256)
            CP_ASYNC16(sW_addr + j * 16, src + j * 16);
        CP_COMMIT();
    }
    if (t < COUT) sBias[t] = conv_b[t];

    // ---- build x slab: 514 pos x 64 ci, bf16 hi/lo, swizzled [pos][u32] ----
    {
        const float* xb = x + (size_t)b * CIN * HWIN;
        unsigned short* shi = (unsigned short*)sSlabH;
        unsigned short* slo = (unsigned short*)sSlabL;
        for (int idx = t; idx < CIN * 129; idx += 256) {
            int ci   = idx / 129;
            int gi   = idx - ci * 129;
            int pos0 = gi * 4;
            float v[4];
            if (pos0 + 3 < 514 && p0 + pos0 + 4 <= HWIN) {
                float4 f = *(const float4*)(xb + (size_t)ci * HWIN + p0 + pos0);
                v[0] = f.x; v[1] = f.y; v[2] = f.z; v[3] = f.w;
            } else {
#pragma unroll
                for (int e = 0; e < 4; e++) {
                    int pos = pos0 + e;
                    v[e] = (pos < 514 && p0 + pos < HWIN)
                         ? xb[(size_t)ci * HWIN + p0 + pos] : 0.f;
                }
            }
#pragma unroll
            for (int e = 0; e < 4; e++) {
                int pos = pos0 + e;
                if (pos >= 514) break;
                __nv_bfloat16 h = __float2bfloat16(v[e]);
                __nv_bfloat16 l = __float2bfloat16(v[e] - __bfloat162float(h));
                uint32_t word = (uint32_t)(pos * 33) +
                                ((uint32_t)(ci >> 1) ^ (uint32_t)((pos & 7) << 2));
                shi[word * 2 + (ci & 1)] = *(unsigned short*)&h;
                slo[word * 2 + (ci & 1)] = *(unsigned short*)&l;
            }
        }
    }
    CP_WAIT0();
    __syncthreads();

    // B address precompute (constant across taps/kc)
    int coB[8], coK[8];
#pragma unroll
    for (int n = 0; n < 8; n++) {
        int co = warp_n + n * 8 + g;
        coB[n] = co * 33;
        coK[n] = (co & 7) << 2;
    }

    float acc[4][8][4];
#pragma unroll
    for (int m = 0; m < 4; m++)
#pragma unroll
        for (int n = 0; n < 8; n++)
#pragma unroll
            for (int e = 0; e < 4; e++) acc[m][n][e] = 0.f;

    for (int tap = 0; tap < 9; tap++) {
        const int buf = tap & 1;
        if (tap < 8) {   // prefetch next tap into other buffer (safe: synced)
            const char* src = (const char*)(g_w + (tap + 1) * WTAP_U32);
            const uint32_t dst = sW_addr + (buf ^ 1) * WTAP_B;
            for (int j = t; j < 2112; j += 256)
                CP_ASYNC16(dst + j * 16, src + j * 16);
            CP_COMMIT();
        }
        const uint32_t* WH = sW + buf * WTAP_U32;
        const uint32_t* WL = WH + 4224;

        const int off = (tap / 3) * 128 + (tap % 3);
        int baseA[4], keyA[4], baseB[4], keyB[4];
#pragma unroll
        for (int m = 0; m < 4; m++) {
            int pa = warp_m + m * 16 + g + off;
            int pb = pa + 8;
            baseA[m] = pa * 33; keyA[m] = (pa & 7) << 2;
            baseB[m] = pb * 33; keyB[m] = (pb & 7) << 2;
        }

#pragma unroll
        for (int kc = 0; kc < 4; kc++) {
            const int k0 = kc * 8 + tl;
            const int k1 = k0 + 4;
            uint32_t ah[4][4], al[4][4];
#pragma unroll
            for (int m = 0; m < 4; m++) {
                ah[m][0] = sSlabH[baseA[m] + (k0 ^ keyA[m])];
                ah[m][1] = sSlabH[baseB[m] + (k0 ^ keyB[m])];
                ah[m][2] = sSlabH[baseA[m] + (k1 ^ keyA[m])];
                ah[m][3] = sSlabH[baseB[m] + (k1 ^ keyB[m])];
                al[m][0] = sSlabL[baseA[m] + (k0 ^ keyA[m])];
                al[m][1] = sSlabL[baseB[m] + (k0 ^ keyB[m])];
                al[m][2] = sSlabL[baseA[m] + (k1 ^ keyA[m])];
                al[m][3] = sSlabL[baseB[m] + (k1 ^ keyB[m])];
            }
#pragma unroll
            for (int n = 0; n < 8; n++) {
                uint32_t bh[2], bl[2];
                bh[0] = WH[coB[n] + (k0 ^ coK[n])];
                bh[1] = WH[coB[n] + (k1 ^ coK[n])];
                bl[0] = WL[coB[n] + (k0 ^ coK[n])];
                bl[1] = WL[coB[n] + (k1 ^ coK[n])];
#pragma unroll
                for (int m = 0; m < 4; m++) {
                    mma16816(acc[m][n], ah[m], bh);   // hi*hi
                    mma16816(acc[m][n], ah[m], bl);   // hi*lo
                    mma16816(acc[m][n], al[m], bh);   // lo*hi
                }
            }
        }
        if (tap < 8) CP_WAIT0();
        __syncthreads();
    }

    // ---- epilogue: bias, store y, deterministic per-group partials ----
#pragma unroll
    for (int n = 0; n < 8; n++) {
        const int co0 = warp_n + n * 8 + tl * 2;
        const int co1 = co0 + 1;
        const float b0 = sBias[co0];
        const float b1 = sBias[co1];
        float s = 0.f, q = 0.f;
#pragma unroll
        for (int m = 0; m < 4; m++) {
            const int pa = warp_m + m * 16 + g;
            const int pb = pa + 8;
            const int wA = pa & 127, hA = 2 * i + (pa >> 7);
            const int wB = pb & 127, hB = 2 * i + (pb >> 7);
            float v0 = acc[m][n][0] + b0;
            float v1 = acc[m][n][1] + b1;
            float v2 = acc[m][n][2] + b0;
            float v3 = acc[m][n][3] + b1;
            if (wA < 126) {
                size_t iy = ((size_t)(b * COUT + co0) * HO + hA) * WO + wA;
                g_y[iy] = v0;
                g_y[iy + (size_t)HO * WO] = v1;
                s += v0 + v1; q += v0 * v0 + v1 * v1;
            }
            if (wB < 126) {
                size_t iy = ((size_t)(b * COUT + co0) * HO + hB) * WO + wB;
                g_y[iy] = v2;
                g_y[iy + (size_t)HO * WO] = v3;
                s += v2 + v3; q += v2 * v2 + v3 * v3;
            }
        }
#pragma unroll
        for (int o = 16; o > 0; o >>= 1) {
            s += __shfl_xor_sync(0xffffffffu, s, o);
            q += __shfl_xor_sync(0xffffffffu, q, o);
        }
        if (lane == 0) {
            sRed [(wn * 8 + n) * 4 + wm] = s;
            sRedQ[(wn * 8 + n) * 4 + wm] = q;
        }
    }
    __syncthreads();
    if (t < 16) {
        float S = 0.f, Q = 0.f;
#pragma unroll
        for (int k = 0; k < 4; k++) { S += sRed[t * 4 + k]; Q += sRedQ[t * 4 + k]; }
        g_psum[(b * NGRP + t) * NTILE + i] = S;
        g_psq [(b * NGRP + t) * NTILE + i] = Q;
    }
}

// ---------------------------------------------------------------------------
__global__ void stats_kernel() {
    int i = blockIdx.x * blockDim.x + threadIdx.x;
    if (i < BATCH * NGRP) {
        float s = 0.f, q = 0.f;
        const float* ps = g_psum + i * NTILE;
        const float* pq = g_psq  + i * NTILE;
        for (int tl = 0; tl < NTILE; tl++) { s += ps[tl]; q += pq[tl]; }
        const float invN = 1.f / (float)GN_N;
        float mean = s * invN;
        float var  = q * invN - mean * mean;
        g_mean[i] = mean;
        g_rstd[i] = rsqrtf(var + 1e-5f);
    }
}

// ---------------------------------------------------------------------------
__global__ void pool_kernel(const float* __restrict__ gn_w,
                            const float* __restrict__ gn_b,
                            const float* __restrict__ scale,
                            float* __restrict__ out) {
    int idx = blockIdx.x * blockDim.x + threadIdx.x;
    if (idx >= BATCH * COUT * HP * WP) return;
    int ow  = idx % WP;
    int tmp = idx / WP;
    int oh  = tmp % HP;
    tmp    /= HP;
    int c   = tmp % COUT;
    int b   = tmp / COUT;

    const int bg = b * NGRP + (c >> 3);
    const float mean = g_mean[bg];
    const float rstd = g_rstd[bg];
    const float a  = rstd * gn_w[c] * scale[c];
    const float bb = (gn_b[c] - mean * rstd * gn_w[c]) * scale[c];

    const float* yp = g_y + (((size_t)b * COUT + c) * HO + oh * 2) * (size_t)WO + ow * 2;
    float v0 = fmaf(a, yp[0],      bb);
    float v1 = fmaf(a, yp[1],      bb);
    float v2 = fmaf(a, yp[WO],     bb);
    float v3 = fmaf(a, yp[WO + 1], bb);
    float m = fmaxf(fmaxf(v0, v1), fmaxf(v2, v3));
    out[idx] = fminf(fmaxf(m, 0.0f), 1.0f);
}

// ---------------------------------------------------------------------------
extern "C" void kernel_launch(void* const* d_in, const int* in_sizes, int n_in,
                              void* d_out, int out_size) {
    const float* x      = (const float*)d_in[0];
    const float* conv_w = (const float*)d_in[1];
    const float* conv_b = (const float*)d_in[2];
    const float* gn_w   = (const float*)d_in[3];
    const float* gn_b   = (const float*)d_in[4];
    const float* scale  = (const float*)d_in[5];
    float* out = (float*)d_out;

    cudaFuncSetAttribute(conv_kernel, cudaFuncAttributeMaxDynamicSharedMemorySize, SMEM_TOTAL);

    prep_kernel<<<(9 * COUT * CIN + 255) / 256, 256>>>(conv_w);
    conv_kernel<<<dim3(NTILE, BATCH), 256, SMEM_TOTAL>>>(x, conv_b);
    stats_kernel<<<2, 256>>>();
    const int npool = BATCH * COUT * HP * WP;
    pool_kernel<<<(npool + 255) / 256, 256>>>(gn_w, gn_b, scale, out);
}

// round 8
// speedup vs baseline: 2.1575x; 1.5182x over previous
#include <cuda_runtime.h>
#include <cuda_bf16.h>
#include <cstdint>
#include <math.h>

// ---------------- problem constants ----------------
#define BATCH 32
#define CIN   64
#define HWIN  16384
#define COUT  128
#define HO    126
#define WO    126
#define NGRP  16
#define HP    63
#define WP    63
#define NTILE 63
#define GN_N  (8 * HO * WO)

// W tile: per tap, [co][33 u32] (32 data + 1 pad), hi then lo: 8448 u32 = 33792 B
#define WTAP_U32 8448
#define WTAP_B   33792

// smem layout (bytes):
//  [0,512)         bias (128 f)
//  [512,1024)      sRed  (128 f)
//  [1024,1536)     sRedQ (128 f)
//  [2048,+67584)   W ping-pong: 2 bufs x 33792 B
//  [69632,+67848)  slab hi: 514*33 u32
//  [137480,+67848) slab lo
#define SM_W     2048
#define SM_SLABH 69632
#define SM_SLABL 137480
#define SMEM_TOTAL 205328

#define NTHREADS 512

// ---------------- helpers ----------------
__device__ __forceinline__ uint32_t smem_u32(const void* p) {
    uint32_t a;
    asm("{ .reg .u64 t; cvta.to.shared.u64 t, %1; cvt.u32.u64 %0, t; }" : "=r"(a) : "l"(p));
    return a;
}
#define CP_ASYNC16(dst_u32, src_ptr) \
    asm volatile("cp.async.cg.shared.global [%0], [%1], 16;" :: "r"(dst_u32), "l"(src_ptr) : "memory")
#define CP_COMMIT() asm volatile("cp.async.commit_group;" ::: "memory")
#define CP_WAIT0()  asm volatile("cp.async.wait_group 0;" ::: "memory")

__device__ __forceinline__ void mma16816(float* c, const uint32_t* a, const uint32_t* b) {
    asm volatile(
        "mma.sync.aligned.m16n8k16.row.col.f32.bf16.bf16.f32 "
        "{%0,%1,%2,%3}, {%4,%5,%6,%7}, {%8,%9}, {%0,%1,%2,%3};"
        : "+f"(c[0]), "+f"(c[1]), "+f"(c[2]), "+f"(c[3])
        : "r"(a[0]), "r"(a[1]), "r"(a[2]), "r"(a[3]), "r"(b[0]), "r"(b[1]));
}

// ---------------- device scratch ----------------
__device__ float g_y[(size_t)BATCH * COUT * HO * WO];            // [b][co][h][w]
__device__ __align__(16) uint32_t g_w[9 * WTAP_U32];             // per-tap swizzled bf16 hi/lo
__device__ float g_psum[BATCH * NGRP * NTILE];
__device__ float g_psq [BATCH * NGRP * NTILE];
__device__ float g_mean[BATCH * NGRP];
__device__ float g_rstd[BATCH * NGRP];

// ---------------------------------------------------------------------------
// Prep: conv_w (O,I,3,3) fp32 -> per-tap [co][swizzled ci-u32] bf16 hi/lo.
// swizzle: u32 index (ci>>1) ^ ((co&7)<<2); pad word zeroed.
// ---------------------------------------------------------------------------
__global__ void prep_kernel(const float* __restrict__ conv_w) {
    int idx = blockIdx.x * 256 + threadIdx.x;
    if (idx >= 9 * COUT * CIN) return;
    int r   = idx / (COUT * CIN);
    int rem = idx - r * (COUT * CIN);
    int co  = rem >> 6;
    int ci  = rem & 63;
    float w = conv_w[(co * CIN + ci) * 9 + r];
    __nv_bfloat16 h = __float2bfloat16(w);
    __nv_bfloat16 l = __float2bfloat16(w - __bfloat162float(h));
    uint32_t swz = (uint32_t)(ci >> 1) ^ (uint32_t)((co & 7) << 2);
    unsigned short* gw = (unsigned short*)g_w;
    gw[(r * WTAP_U32 +        co * 33 + swz) * 2 + (ci & 1)] = *(unsigned short*)&h;
    gw[(r * WTAP_U32 + 4224 + co * 33 + swz) * 2 + (ci & 1)] = *(unsigned short*)&l;
    if (ci == 0) {           // zero pad words (copied by cp.async, never read)
        g_w[r * WTAP_U32 +        co * 33 + 32] = 0;
        g_w[r * WTAP_U32 + 4224 + co * 33 + 32] = 0;
    }
}

// ---------------------------------------------------------------------------
// Conv via mma.sync m16n8k16 bf16, split hi/lo (hh + hl + lh), fp32 acc.
// CTA = (row-pair i, batch b): M=256 pos x N=128 co x K=576.
// 512 threads, 16 warps: 8(M) x 2(N); warp tile 32x64 -> 64 acc regs/thread.
// ---------------------------------------------------------------------------
__global__ __launch_bounds__(NTHREADS, 1)
void conv_kernel(const float* __restrict__ x, const float* __restrict__ conv_b) {
    extern __shared__ char smem[];
    float*    sBias  = (float*)smem;
    float*    sRed   = (float*)(smem + 512);
    float*    sRedQ  = (float*)(smem + 1024);
    uint32_t* sW     = (uint32_t*)(smem + SM_W);
    uint32_t* sSlabH = (uint32_t*)(smem + SM_SLABH);
    uint32_t* sSlabL = (uint32_t*)(smem + SM_SLABL);

    const int t    = threadIdx.x;
    const int wid  = t >> 5;
    const int lane = t & 31;
    const int g    = lane >> 2;
    const int tl   = lane & 3;
    const int wm   = wid & 7;            // M warp index (0..7)
    const int wn   = wid >> 3;           // N warp index (0..1)
    const int warp_m = wm * 32;
    const int warp_n = wn * 64;
    const int i  = blockIdx.x;           // row pair: output rows 2i, 2i+1
    const int b  = blockIdx.y;
    const int p0 = i * 256;

    const uint32_t sW_addr = smem_u32(sW);

    // prefetch W tap 0 -> buf 0
    {
        const char* src = (const char*)g_w;
        for (int j = t; j < 2112; j += NTHREADS)
            CP_ASYNC16(sW_addr + j * 16, src + j * 16);
        CP_COMMIT();
    }
    if (t < COUT) sBias[t] = conv_b[t];

    // ---- build x slab: 514 pos x 64 ci, bf16 hi/lo, swizzled [pos][u32] ----
    {
        const float* xb = x + (size_t)b * CIN * HWIN;
        unsigned short* shi = (unsigned short*)sSlabH;
        unsigned short* slo = (unsigned short*)sSlabL;
        for (int idx = t; idx < CIN * 129; idx += NTHREADS) {
            int ci   = idx / 129;
            int gi   = idx - ci * 129;
            int pos0 = gi * 4;
            float v[4];
            if (pos0 + 3 < 514 && p0 + pos0 + 4 <= HWIN) {
                float4 f = *(const float4*)(xb + (size_t)ci * HWIN + p0 + pos0);
                v[0] = f.x; v[1] = f.y; v[2] = f.z; v[3] = f.w;
            } else {
#pragma unroll
                for (int e = 0; e < 4; e++) {
                    int pos = pos0 + e;
                    v[e] = (pos < 514 && p0 + pos < HWIN)
                         ? xb[(size_t)ci * HWIN + p0 + pos] : 0.f;
                }
            }
#pragma unroll
            for (int e = 0; e < 4; e++) {
                int pos = pos0 + e;
                if (pos >= 514) break;
                __nv_bfloat16 h = __float2bfloat16(v[e]);
                __nv_bfloat16 l = __float2bfloat16(v[e] - __bfloat162float(h));
                uint32_t word = (uint32_t)(pos * 33) +
                                ((uint32_t)(ci >> 1) ^ (uint32_t)((pos & 7) << 2));
                shi[word * 2 + (ci & 1)] = *(unsigned short*)&h;
                slo[word * 2 + (ci & 1)] = *(unsigned short*)&l;
            }
        }
    }
    CP_WAIT0();
    __syncthreads();

    // B address precompute (constant across taps/kc)
    int coB[8], coK[8];
#pragma unroll
    for (int n = 0; n < 8; n++) {
        int co = warp_n + n * 8 + g;
        coB[n] = co * 33;
        coK[n] = (co & 7) << 2;
    }

    float acc[2][8][4];
#pragma unroll
    for (int m = 0; m < 2; m++)
#pragma unroll
        for (int n = 0; n < 8; n++)
#pragma unroll
            for (int e = 0; e < 4; e++) acc[m][n][e] = 0.f;

    for (int tap = 0; tap < 9; tap++) {
        const int buf = tap & 1;
        if (tap < 8) {   // prefetch next tap into other buffer (safe: synced)
            const char* src = (const char*)(g_w + (tap + 1) * WTAP_U32);
            const uint32_t dst = sW_addr + (buf ^ 1) * WTAP_B;
            for (int j = t; j < 2112; j += NTHREADS)
                CP_ASYNC16(dst + j * 16, src + j * 16);
            CP_COMMIT();
        }
        const uint32_t* WH = sW + buf * WTAP_U32;
        const uint32_t* WL = WH + 4224;

        const int off = (tap / 3) * 128 + (tap % 3);
        int baseA[2], keyA[2], baseB[2], keyB[2];
#pragma unroll
        for (int m = 0; m < 2; m++) {
            int pa = warp_m + m * 16 + g + off;
            int pb = pa + 8;
            baseA[m] = pa * 33; keyA[m] = (pa & 7) << 2;
            baseB[m] = pb * 33; keyB[m] = (pb & 7) << 2;
        }

#pragma unroll
        for (int kc = 0; kc < 4; kc++) {
            const int k0 = kc * 8 + tl;
            const int k1 = k0 + 4;
            uint32_t ah[2][4], al[2][4];
#pragma unroll
            for (int m = 0; m < 2; m++) {
                ah[m][0] = sSlabH[baseA[m] + (k0 ^ keyA[m])];
                ah[m][1] = sSlabH[baseB[m] + (k0 ^ keyB[m])];
                ah[m][2] = sSlabH[baseA[m] + (k1 ^ keyA[m])];
                ah[m][3] = sSlabH[baseB[m] + (k1 ^ keyB[m])];
                al[m][0] = sSlabL[baseA[m] + (k0 ^ keyA[m])];
                al[m][1] = sSlabL[baseB[m] + (k0 ^ keyB[m])];
                al[m][2] = sSlabL[baseA[m] + (k1 ^ keyA[m])];
                al[m][3] = sSlabL[baseB[m] + (k1 ^ keyB[m])];
            }
#pragma unroll
            for (int n = 0; n < 8; n++) {
                uint32_t bh[2], bl[2];
                bh[0] = WH[coB[n] + (k0 ^ coK[n])];
                bh[1] = WH[coB[n] + (k1 ^ coK[n])];
                bl[0] = WL[coB[n] + (k0 ^ coK[n])];
                bl[1] = WL[coB[n] + (k1 ^ coK[n])];
#pragma unroll
                for (int m = 0; m < 2; m++) {
                    mma16816(acc[m][n], ah[m], bh);   // hi*hi
                    mma16816(acc[m][n], ah[m], bl);   // hi*lo
                    mma16816(acc[m][n], al[m], bh);   // lo*hi
                }
            }
        }
        if (tap < 8) CP_WAIT0();
        __syncthreads();
    }

    // ---- epilogue: bias, store y, deterministic per-group partials ----
#pragma unroll
    for (int n = 0; n < 8; n++) {
        const int co0 = warp_n + n * 8 + tl * 2;
        const int co1 = co0 + 1;
        const float b0 = sBias[co0];
        const float b1 = sBias[co1];
        float s = 0.f, q = 0.f;
#pragma unroll
        for (int m = 0; m < 2; m++) {
            const int pa = warp_m + m * 16 + g;
            const int pb = pa + 8;
            const int wA = pa & 127, hA = 2 * i + (pa >> 7);
            const int wB = pb & 127, hB = 2 * i + (pb >> 7);
            float v0 = acc[m][n][0] + b0;
            float v1 = acc[m][n][1] + b1;
            float v2 = acc[m][n][2] + b0;
            float v3 = acc[m][n][3] + b1;
            if (wA < 126) {
                size_t iy = ((size_t)(b * COUT + co0) * HO + hA) * WO + wA;
                g_y[iy] = v0;
                g_y[iy + (size_t)HO * WO] = v1;
                s += v0 + v1; q += v0 * v0 + v1 * v1;
            }
            if (wB < 126) {
                size_t iy = ((size_t)(b * COUT + co0) * HO + hB) * WO + wB;
                g_y[iy] = v2;
                g_y[iy + (size_t)HO * WO] = v3;
                s += v2 + v3; q += v2 * v2 + v3 * v3;
            }
        }
#pragma unroll
        for (int o = 16; o > 0; o >>= 1) {
            s += __shfl_xor_sync(0xffffffffu, s, o);
            q += __shfl_xor_sync(0xffffffffu, q, o);
        }
        if (lane == 0) {
            sRed [(wn * 8 + n) * 8 + wm] = s;
            sRedQ[(wn * 8 + n) * 8 + wm] = q;
        }
    }
    __syncthreads();
    if (t < 16) {
        float S = 0.f, Q = 0.f;
#pragma unroll
        for (int k = 0; k < 8; k++) { S += sRed[t * 8 + k]; Q += sRedQ[t * 8 + k]; }
        g_psum[(b * NGRP + t) * NTILE + i] = S;
        g_psq [(b * NGRP + t) * NTILE + i] = Q;
    }
}

// ---------------------------------------------------------------------------
__global__ void stats_kernel() {
    int i = blockIdx.x * blockDim.x + threadIdx.x;
    if (i < BATCH * NGRP) {
        float s = 0.f, q = 0.f;
        const float* ps = g_psum + i * NTILE;
        const float* pq = g_psq  + i * NTILE;
        for (int tl = 0; tl < NTILE; tl++) { s += ps[tl]; q += pq[tl]; }
        const float invN = 1.f / (float)GN_N;
        float mean = s * invN;
        float var  = q * invN - mean * mean;
        g_mean[i] = mean;
        g_rstd[i] = rsqrtf(var + 1e-5f);
    }
}

// ---------------------------------------------------------------------------
__global__ void pool_kernel(const float* __restrict__ gn_w,
                            const float* __restrict__ gn_b,
                            const float* __restrict__ scale,
                            float* __restrict__ out) {
    int idx = blockIdx.x * blockDim.x + threadIdx.x;
    if (idx >= BATCH * COUT * HP * WP) return;
    int ow  = idx % WP;
    int tmp = idx / WP;
    int oh  = tmp % HP;
    tmp    /= HP;
    int c   = tmp % COUT;
    int b   = tmp / COUT;

    const int bg = b * NGRP + (c >> 3);
    const float mean = g_mean[bg];
    const float rstd = g_rstd[bg];
    const float a  = rstd * gn_w[c] * scale[c];
    const float bb = (gn_b[c] - mean * rstd * gn_w[c]) * scale[c];

    const float* yp = g_y + (((size_t)b * COUT + c) * HO + oh * 2) * (size_t)WO + ow * 2;
    float v0 = fmaf(a, yp[0],      bb);
    float v1 = fmaf(a, yp[1],      bb);
    float v2 = fmaf(a, yp[WO],     bb);
    float v3 = fmaf(a, yp[WO + 1], bb);
    float m = fmaxf(fmaxf(v0, v1), fmaxf(v2, v3));
    out[idx] = fminf(fmaxf(m, 0.0f), 1.0f);
}

// ---------------------------------------------------------------------------
extern "C" void kernel_launch(void* const* d_in, const int* in_sizes, int n_in,
                              void* d_out, int out_size) {
    const float* x      = (const float*)d_in[0];
    const float* conv_w = (const float*)d_in[1];
    const float* conv_b = (const float*)d_in[2];
    const float* gn_w   = (const float*)d_in[3];
    const float* gn_b   = (const float*)d_in[4];
    const float* scale  = (const float*)d_in[5];
    float* out = (float*)d_out;

    cudaFuncSetAttribute(conv_kernel, cudaFuncAttributeMaxDynamicSharedMemorySize, SMEM_TOTAL);

    prep_kernel<<<(9 * COUT * CIN + 255) / 256, 256>>>(conv_w);
    conv_kernel<<<dim3(NTILE, BATCH), NTHREADS, SMEM_TOTAL>>>(x, conv_b);
    stats_kernel<<<2, 256>>>();
    const int npool = BATCH * COUT * HP * WP;
    pool_kernel<<<(npool + 255) / 256, 256>>>(gn_w, gn_b, scale, out);
}